// round 2
// baseline (speedup 1.0000x reference)
#include <cuda_runtime.h>
#include <math.h>
#include <stdint.h>

#define BATCH 2
#define SEQ 2048
#define DM 1024
#define NH 16
#define DK 64
#define MROWS (BATCH * SEQ)          // 4096
#define BH (BATCH * NH)              // 32

// Scratch (allocation-free rule: __device__ globals)
__device__ float g_q[BH * SEQ * DK];     // [b,h,s,dk]
__device__ float g_k[BH * SEQ * DK];
__device__ float g_v[BH * SEQ * DK];
__device__ float g_ctx[MROWS * DM];      // [b*s, h*dk] concat layout

// ---------------------------------------------------------------------------
// Kernel 1: QKV projection.  y = x @ W^T  (NT gemm, both operands K-contiguous)
// M=4096, N=1024, K=1024. blockIdx.z selects Q/K/V. Output in head-major layout.
// Tile 64x64, BK=16, 256 threads, 4x4 microtile per thread.
// ---------------------------------------------------------------------------
__global__ void __launch_bounds__(256)
proj_qkv_kernel(const float* __restrict__ x,
                const float* __restrict__ wq,
                const float* __restrict__ wk,
                const float* __restrict__ wv)
{
    const float* w   = (blockIdx.z == 0) ? wq : (blockIdx.z == 1) ? wk : wv;
    float*       out = (blockIdx.z == 0) ? g_q : (blockIdx.z == 1) ? g_k : g_v;

    __shared__ float As[16][64];
    __shared__ float Bs[16][64];

    const int tx = threadIdx.x, ty = threadIdx.y;
    const int t  = ty * 16 + tx;
    const int m0 = blockIdx.y * 64;
    const int n0 = blockIdx.x * 64;
    const int lr = t >> 2;          // 0..63 (tile row)
    const int lk = (t & 3) * 4;     // 0,4,8,12 (k offset)

    float acc[4][4] = {};

    for (int k0 = 0; k0 < DM; k0 += 16) {
        float4 a4 = *(const float4*)(x + (size_t)(m0 + lr) * DM + k0 + lk);
        float4 b4 = *(const float4*)(w + (size_t)(n0 + lr) * DM + k0 + lk);
        As[lk + 0][lr] = a4.x; As[lk + 1][lr] = a4.y;
        As[lk + 2][lr] = a4.z; As[lk + 3][lr] = a4.w;
        Bs[lk + 0][lr] = b4.x; Bs[lk + 1][lr] = b4.y;
        Bs[lk + 2][lr] = b4.z; Bs[lk + 3][lr] = b4.w;
        __syncthreads();
        #pragma unroll
        for (int k = 0; k < 16; k++) {
            float4 av = *(float4*)&As[k][ty * 4];
            float4 bv = *(float4*)&Bs[k][tx * 4];
            float a[4] = {av.x, av.y, av.z, av.w};
            float b[4] = {bv.x, bv.y, bv.z, bv.w};
            #pragma unroll
            for (int i = 0; i < 4; i++)
                #pragma unroll
                for (int j = 0; j < 4; j++)
                    acc[i][j] = fmaf(a[i], b[j], acc[i][j]);
        }
        __syncthreads();
    }

    #pragma unroll
    for (int i = 0; i < 4; i++) {
        int m = m0 + ty * 4 + i;
        int b = m / SEQ, s = m % SEQ;
        #pragma unroll
        for (int j = 0; j < 4; j++) {
            int n = n0 + tx * 4 + j;
            int h = n / DK, d = n % DK;
            out[((size_t)(b * NH + h) * SEQ + s) * DK + d] = acc[i][j];
        }
    }
}

// ---------------------------------------------------------------------------
// Kernel 2: scores = (Q @ K^T) * 1/8, masked (-1e9 where mask!=0).
// Per (b,h): M=2048 (q), N=2048 (kv), K=64. NT gemm, writes pre-softmax attn.
// ---------------------------------------------------------------------------
__global__ void __launch_bounds__(256)
scores_kernel(const int* __restrict__ mask, float* __restrict__ attn)
{
    const int bh = blockIdx.z;
    const int b  = bh >> 4;
    const float* Q = g_q + (size_t)bh * SEQ * DK;
    const float* K = g_k + (size_t)bh * SEQ * DK;

    __shared__ float As[16][64];
    __shared__ float Bs[16][64];

    const int tx = threadIdx.x, ty = threadIdx.y;
    const int t  = ty * 16 + tx;
    const int m0 = blockIdx.y * 64;
    const int n0 = blockIdx.x * 64;
    const int lr = t >> 2;
    const int lk = (t & 3) * 4;

    float acc[4][4] = {};

    for (int k0 = 0; k0 < DK; k0 += 16) {
        float4 a4 = *(const float4*)(Q + (size_t)(m0 + lr) * DK + k0 + lk);
        float4 b4 = *(const float4*)(K + (size_t)(n0 + lr) * DK + k0 + lk);
        As[lk + 0][lr] = a4.x; As[lk + 1][lr] = a4.y;
        As[lk + 2][lr] = a4.z; As[lk + 3][lr] = a4.w;
        Bs[lk + 0][lr] = b4.x; Bs[lk + 1][lr] = b4.y;
        Bs[lk + 2][lr] = b4.z; Bs[lk + 3][lr] = b4.w;
        __syncthreads();
        #pragma unroll
        for (int k = 0; k < 16; k++) {
            float4 av = *(float4*)&As[k][ty * 4];
            float4 bv = *(float4*)&Bs[k][tx * 4];
            float a[4] = {av.x, av.y, av.z, av.w};
            float bb[4] = {bv.x, bv.y, bv.z, bv.w};
            #pragma unroll
            for (int i = 0; i < 4; i++)
                #pragma unroll
                for (int j = 0; j < 4; j++)
                    acc[i][j] = fmaf(a[i], bb[j], acc[i][j]);
        }
        __syncthreads();
    }

    int mk[4];
    #pragma unroll
    for (int j = 0; j < 4; j++)
        mk[j] = mask[b * SEQ + n0 + tx * 4 + j];

    #pragma unroll
    for (int i = 0; i < 4; i++) {
        int m = m0 + ty * 4 + i;
        float* row = attn + ((size_t)bh * SEQ + m) * SEQ;
        #pragma unroll
        for (int j = 0; j < 4; j++) {
            int n = n0 + tx * 4 + j;
            float v = acc[i][j] * 0.125f;          // 1/sqrt(64)
            if (mk[j]) v = -1e9f;
            row[n] = v;
        }
    }
}

// ---------------------------------------------------------------------------
// Kernel 3: row softmax in place. One block (256 thr) per row of 2048.
// ---------------------------------------------------------------------------
__global__ void __launch_bounds__(256)
softmax_kernel(float* __restrict__ attn)
{
    float* p = attn + (size_t)blockIdx.x * SEQ;
    const int t = threadIdx.x;

    float vals[8];
    float mx = -INFINITY;
    #pragma unroll
    for (int c = 0; c < 2; c++) {
        float4 f = *(float4*)(p + c * 1024 + t * 4);
        vals[c * 4 + 0] = f.x; vals[c * 4 + 1] = f.y;
        vals[c * 4 + 2] = f.z; vals[c * 4 + 3] = f.w;
    }
    #pragma unroll
    for (int i = 0; i < 8; i++) mx = fmaxf(mx, vals[i]);

    __shared__ float sm[8];
    #pragma unroll
    for (int o = 16; o; o >>= 1) mx = fmaxf(mx, __shfl_xor_sync(0xffffffffu, mx, o));
    if ((t & 31) == 0) sm[t >> 5] = mx;
    __syncthreads();
    if (t < 32) {
        float v = (t < 8) ? sm[t] : -INFINITY;
        #pragma unroll
        for (int o = 4; o; o >>= 1) v = fmaxf(v, __shfl_xor_sync(0xffffffffu, v, o));
        if (t == 0) sm[0] = v;
    }
    __syncthreads();
    mx = sm[0];

    float s = 0.f;
    #pragma unroll
    for (int i = 0; i < 8; i++) { vals[i] = __expf(vals[i] - mx); s += vals[i]; }

    __shared__ float sm2[8];
    #pragma unroll
    for (int o = 16; o; o >>= 1) s += __shfl_xor_sync(0xffffffffu, s, o);
    if ((t & 31) == 0) sm2[t >> 5] = s;
    __syncthreads();
    if (t < 32) {
        float v = (t < 8) ? sm2[t] : 0.f;
        #pragma unroll
        for (int o = 4; o; o >>= 1) v += __shfl_xor_sync(0xffffffffu, v, o);
        if (t == 0) sm2[0] = v;
    }
    __syncthreads();
    const float inv = 1.0f / sm2[0];

    #pragma unroll
    for (int c = 0; c < 2; c++) {
        float4 f;
        f.x = vals[c * 4 + 0] * inv; f.y = vals[c * 4 + 1] * inv;
        f.z = vals[c * 4 + 2] * inv; f.w = vals[c * 4 + 3] * inv;
        *(float4*)(p + c * 1024 + t * 4) = f;
    }
}

// ---------------------------------------------------------------------------
// Kernel 4: ctx = attn @ V.  Per (b,h): M=2048, N=64 (dk), K=2048. NN gemm.
// Writes ctx into concat layout [b*s, h*dk].
// ---------------------------------------------------------------------------
__global__ void __launch_bounds__(256)
ctx_kernel(const float* __restrict__ attn)
{
    const int bh = blockIdx.z;
    const int b = bh >> 4, h = bh & 15;
    const float* A = attn + (size_t)bh * SEQ * SEQ;   // [2048,2048]
    const float* V = g_v  + (size_t)bh * SEQ * DK;    // [2048,64]

    __shared__ float As[16][64];
    __shared__ float Bs[16][64];

    const int tx = threadIdx.x, ty = threadIdx.y;
    const int t  = ty * 16 + tx;
    const int m0 = blockIdx.y * 64;
    const int lra = t >> 2;          // A: tile row 0..63
    const int lka = (t & 3) * 4;     // A: k offset
    const int lrb = t >> 4;          // B: k row 0..15
    const int lnb = (t & 15) * 4;    // B: n offset 0..60

    float acc[4][4] = {};

    for (int k0 = 0; k0 < SEQ; k0 += 16) {
        float4 a4 = *(const float4*)(A + (size_t)(m0 + lra) * SEQ + k0 + lka);
        As[lka + 0][lra] = a4.x; As[lka + 1][lra] = a4.y;
        As[lka + 2][lra] = a4.z; As[lka + 3][lra] = a4.w;
        float4 b4 = *(const float4*)(V + (size_t)(k0 + lrb) * DK + lnb);
        *(float4*)&Bs[lrb][lnb] = b4;
        __syncthreads();
        #pragma unroll
        for (int k = 0; k < 16; k++) {
            float4 av = *(float4*)&As[k][ty * 4];
            float4 bv = *(float4*)&Bs[k][tx * 4];
            float a[4] = {av.x, av.y, av.z, av.w};
            float bb[4] = {bv.x, bv.y, bv.z, bv.w};
            #pragma unroll
            for (int i = 0; i < 4; i++)
                #pragma unroll
                for (int j = 0; j < 4; j++)
                    acc[i][j] = fmaf(a[i], bb[j], acc[i][j]);
        }
        __syncthreads();
    }

    #pragma unroll
    for (int i = 0; i < 4; i++) {
        int m = m0 + ty * 4 + i;                       // q position
        #pragma unroll
        for (int j = 0; j < 4; j++) {
            int d = tx * 4 + j;                        // head dim
            g_ctx[((size_t)b * SEQ + m) * DM + h * DK + d] = acc[i][j];
        }
    }
}

// ---------------------------------------------------------------------------
// Kernel 5: out = ctx @ Wo^T.  M=4096, N=1024, K=1024. NT gemm, plain layout.
// ---------------------------------------------------------------------------
__global__ void __launch_bounds__(256)
outproj_kernel(const float* __restrict__ wo, float* __restrict__ out)
{
    __shared__ float As[16][64];
    __shared__ float Bs[16][64];

    const int tx = threadIdx.x, ty = threadIdx.y;
    const int t  = ty * 16 + tx;
    const int m0 = blockIdx.y * 64;
    const int n0 = blockIdx.x * 64;
    const int lr = t >> 2;
    const int lk = (t & 3) * 4;

    float acc[4][4] = {};

    for (int k0 = 0; k0 < DM; k0 += 16) {
        float4 a4 = *(const float4*)(g_ctx + (size_t)(m0 + lr) * DM + k0 + lk);
        float4 b4 = *(const float4*)(wo    + (size_t)(n0 + lr) * DM + k0 + lk);
        As[lk + 0][lr] = a4.x; As[lk + 1][lr] = a4.y;
        As[lk + 2][lr] = a4.z; As[lk + 3][lr] = a4.w;
        Bs[lk + 0][lr] = b4.x; Bs[lk + 1][lr] = b4.y;
        Bs[lk + 2][lr] = b4.z; Bs[lk + 3][lr] = b4.w;
        __syncthreads();
        #pragma unroll
        for (int k = 0; k < 16; k++) {
            float4 av = *(float4*)&As[k][ty * 4];
            float4 bv = *(float4*)&Bs[k][tx * 4];
            float a[4] = {av.x, av.y, av.z, av.w};
            float bb[4] = {bv.x, bv.y, bv.z, bv.w};
            #pragma unroll
            for (int i = 0; i < 4; i++)
                #pragma unroll
                for (int j = 0; j < 4; j++)
                    acc[i][j] = fmaf(a[i], bb[j], acc[i][j]);
        }
        __syncthreads();
    }

    #pragma unroll
    for (int i = 0; i < 4; i++) {
        int m = m0 + ty * 4 + i;
        #pragma unroll
        for (int j = 0; j < 4; j++) {
            int n = n0 + tx * 4 + j;
            out[(size_t)m * DM + n] = acc[i][j];
        }
    }
}

// ---------------------------------------------------------------------------
// Launch. d_out layout: [out: 4096*1024 f32][attn: 32*2048*2048 f32]
// Inputs (metadata order): x, mask, w_q, w_k, w_v, w_o
// ---------------------------------------------------------------------------
extern "C" void kernel_launch(void* const* d_in, const int* in_sizes, int n_in,
                              void* d_out, int out_size)
{
    const float* x    = (const float*)d_in[0];
    const int*   mask = (const int*)  d_in[1];
    const float* wq   = (const float*)d_in[2];
    const float* wk   = (const float*)d_in[3];
    const float* wv   = (const float*)d_in[4];
    const float* wo   = (const float*)d_in[5];

    float* out  = (float*)d_out;
    float* attn = out + (size_t)MROWS * DM;

    dim3 blk(16, 16);
    proj_qkv_kernel<<<dim3(DM / 64, MROWS / 64, 3), blk>>>(x, wq, wk, wv);
    scores_kernel  <<<dim3(SEQ / 64, SEQ / 64, BH), blk>>>(mask, attn);
    softmax_kernel <<<BH * SEQ, 256>>>(attn);
    ctx_kernel     <<<dim3(1, SEQ / 64, BH), blk>>>(attn);
    outproj_kernel <<<dim3(DM / 64, MROWS / 64, 1), blk>>>(wo, out);
}

// round 5
// speedup vs baseline: 2.1179x; 2.1179x over previous
#include <cuda_runtime.h>
#include <cuda_bf16.h>
#include <math.h>
#include <stdint.h>

#define BATCH 2
#define SEQ 2048
#define DM 1024
#define NH 16
#define DK 64
#define MROWS (BATCH * SEQ)          // 4096
#define BH (BATCH * NH)              // 32

// Scratch (allocation-free rule: __device__ globals)
__device__ float g_q[BH * SEQ * DK];     // [b,h,s,dk]
__device__ float g_k[BH * SEQ * DK];
__device__ float g_v[BH * SEQ * DK];
__device__ float g_ctx[MROWS * DM];      // [b*s, h*dk]

// ---------------------------------------------------------------------------
// bf16 split-precision mma helpers (3xBF16 ~= fp32 accuracy, err ~1e-5)
// ---------------------------------------------------------------------------
__device__ __forceinline__ void mma_bf16(float c[4], const uint32_t a[4], const uint32_t b[2]) {
    asm volatile(
        "mma.sync.aligned.m16n8k16.row.col.f32.bf16.bf16.f32 "
        "{%0,%1,%2,%3}, {%4,%5,%6,%7}, {%8,%9}, {%0,%1,%2,%3};\n"
        : "+f"(c[0]), "+f"(c[1]), "+f"(c[2]), "+f"(c[3])
        : "r"(a[0]), "r"(a[1]), "r"(a[2]), "r"(a[3]), "r"(b[0]), "r"(b[1]));
}

__device__ __forceinline__ void split_pack(float f0, float f1, uint32_t& hi, uint32_t& lo) {
    __nv_bfloat16 h0 = __float2bfloat16_rn(f0);
    __nv_bfloat16 h1 = __float2bfloat16_rn(f1);
    float r0 = f0 - __bfloat162float(h0);
    float r1 = f1 - __bfloat162float(h1);
    __nv_bfloat162 H; H.x = h0; H.y = h1;
    __nv_bfloat162 L; L.x = __float2bfloat16_rn(r0); L.y = __float2bfloat16_rn(r1);
    hi = *reinterpret_cast<uint32_t*>(&H);
    lo = *reinterpret_cast<uint32_t*>(&L);
}

#define SP 136   // padded stride (u32) over m/n dim -> conflict-free frag LDS

// ---------------------------------------------------------------------------
// Unified NT tensor-core GEMM: C[M,N] = A[M,K] @ B[N,K]^T
// Block 128x128, 8 warps (2x4), warp tile 64x32, BK=16, double-buffered smem.
// MODE 0: proj   (A=x, B=wq/wk/wv via z, K=1024, head-major scatter epilogue)
// MODE 1: scores (A=g_q[z], B=g_k[z], K=64, scale+mask epilogue -> attn)
// MODE 2: outproj(A=g_ctx, B=wo, K=1024, plain epilogue)
// ---------------------------------------------------------------------------
template<int MODE>
__global__ void __launch_bounds__(256)
gemm_nt_kernel(const float* __restrict__ Ain, const float* __restrict__ B0,
               const float* __restrict__ B1,  const float* __restrict__ B2,
               const int* __restrict__ mask,  float* __restrict__ outp)
{
    constexpr int KD    = (MODE == 1) ? DK : DM;
    constexpr int NITER = KD / 16;

    __shared__ uint32_t AsH[2][8][SP], AsL[2][8][SP];
    __shared__ uint32_t BsH[2][8][SP], BsL[2][8][SP];

    const int t  = threadIdx.x;
    const int z  = blockIdx.z;
    const int m0 = blockIdx.y * 128;
    const int n0 = blockIdx.x * 128;

    const float* A;
    const float* B;
    if (MODE == 0)      { A = Ain; B = (z == 0) ? B0 : (z == 1) ? B1 : B2; }
    else if (MODE == 1) { A = g_q + (size_t)z * SEQ * DK; B = g_k + (size_t)z * SEQ * DK; }
    else                { A = g_ctx; B = B0; }

    const int lrow = t >> 1;
    const int kc   = (t & 1) * 8;
    const int k2b  = kc >> 1;                  // 0 or 4
    const float* pA = A + (size_t)(m0 + lrow) * KD + kc;
    const float* pB = B + (size_t)(n0 + lrow) * KD + kc;

    float4 ra0 = *(const float4*)(pA);
    float4 ra1 = *(const float4*)(pA + 4);
    float4 rb0 = *(const float4*)(pB);
    float4 rb1 = *(const float4*)(pB + 4);

    split_pack(ra0.x, ra0.y, AsH[0][k2b + 0][lrow], AsL[0][k2b + 0][lrow]);
    split_pack(ra0.z, ra0.w, AsH[0][k2b + 1][lrow], AsL[0][k2b + 1][lrow]);
    split_pack(ra1.x, ra1.y, AsH[0][k2b + 2][lrow], AsL[0][k2b + 2][lrow]);
    split_pack(ra1.z, ra1.w, AsH[0][k2b + 3][lrow], AsL[0][k2b + 3][lrow]);
    split_pack(rb0.x, rb0.y, BsH[0][k2b + 0][lrow], BsL[0][k2b + 0][lrow]);
    split_pack(rb0.z, rb0.w, BsH[0][k2b + 1][lrow], BsL[0][k2b + 1][lrow]);
    split_pack(rb1.x, rb1.y, BsH[0][k2b + 2][lrow], BsL[0][k2b + 2][lrow]);
    split_pack(rb1.z, rb1.w, BsH[0][k2b + 3][lrow], BsL[0][k2b + 3][lrow]);
    __syncthreads();

    const int warp = t >> 5, lane = t & 31;
    const int wm = (warp >> 2) * 64;
    const int wn = (warp & 3) * 32;
    const int qrow = lane >> 2, qk = lane & 3;

    float c[4][4][4] = {};

    for (int it = 0; it < NITER; ++it) {
        const int buf = it & 1;
        if (it + 1 < NITER) {
            const float* qa = pA + (it + 1) * 16;
            const float* qb = pB + (it + 1) * 16;
            ra0 = *(const float4*)(qa); ra1 = *(const float4*)(qa + 4);
            rb0 = *(const float4*)(qb); rb1 = *(const float4*)(qb + 4);
        }

        uint32_t aH[4][4], aL[4][4], bH[4][2], bL[4][2];
        #pragma unroll
        for (int mt = 0; mt < 4; mt++) {
            int m = wm + mt * 16 + qrow;
            aH[mt][0] = AsH[buf][qk][m];     aH[mt][1] = AsH[buf][qk][m + 8];
            aH[mt][2] = AsH[buf][qk + 4][m]; aH[mt][3] = AsH[buf][qk + 4][m + 8];
            aL[mt][0] = AsL[buf][qk][m];     aL[mt][1] = AsL[buf][qk][m + 8];
            aL[mt][2] = AsL[buf][qk + 4][m]; aL[mt][3] = AsL[buf][qk + 4][m + 8];
        }
        #pragma unroll
        for (int nt = 0; nt < 4; nt++) {
            int n = wn + nt * 8 + qrow;
            bH[nt][0] = BsH[buf][qk][n]; bH[nt][1] = BsH[buf][qk + 4][n];
            bL[nt][0] = BsL[buf][qk][n]; bL[nt][1] = BsL[buf][qk + 4][n];
        }
        #pragma unroll
        for (int mt = 0; mt < 4; mt++)
            #pragma unroll
            for (int nt = 0; nt < 4; nt++) {
                mma_bf16(c[mt][nt], aH[mt], bH[nt]);
                mma_bf16(c[mt][nt], aH[mt], bL[nt]);
                mma_bf16(c[mt][nt], aL[mt], bH[nt]);
            }

        if (it + 1 < NITER) {
            const int nb = buf ^ 1;
            split_pack(ra0.x, ra0.y, AsH[nb][k2b + 0][lrow], AsL[nb][k2b + 0][lrow]);
            split_pack(ra0.z, ra0.w, AsH[nb][k2b + 1][lrow], AsL[nb][k2b + 1][lrow]);
            split_pack(ra1.x, ra1.y, AsH[nb][k2b + 2][lrow], AsL[nb][k2b + 2][lrow]);
            split_pack(ra1.z, ra1.w, AsH[nb][k2b + 3][lrow], AsL[nb][k2b + 3][lrow]);
            split_pack(rb0.x, rb0.y, BsH[nb][k2b + 0][lrow], BsL[nb][k2b + 0][lrow]);
            split_pack(rb0.z, rb0.w, BsH[nb][k2b + 1][lrow], BsL[nb][k2b + 1][lrow]);
            split_pack(rb1.x, rb1.y, BsH[nb][k2b + 2][lrow], BsL[nb][k2b + 2][lrow]);
            split_pack(rb1.z, rb1.w, BsH[nb][k2b + 3][lrow], BsL[nb][k2b + 3][lrow]);
        }
        __syncthreads();
    }

    #pragma unroll
    for (int mt = 0; mt < 4; mt++) {
        #pragma unroll
        for (int nt = 0; nt < 4; nt++) {
            int mg = m0 + wm + mt * 16 + qrow;
            int ng = n0 + wn + nt * 8 + qk * 2;
            #pragma unroll
            for (int half = 0; half < 2; half++) {
                int m = mg + half * 8;
                float v0 = c[mt][nt][half * 2 + 0];
                float v1 = c[mt][nt][half * 2 + 1];
                if (MODE == 0) {
                    float* outg = (z == 0) ? g_q : (z == 1) ? g_k : g_v;
                    int b = m >> 11, s = m & (SEQ - 1);
                    int h = ng >> 6, d = ng & 63;
                    float2 w = {v0, v1};
                    *(float2*)(outg + ((size_t)(b * NH + h) * SEQ + s) * DK + d) = w;
                } else if (MODE == 1) {
                    int bb = z >> 4;
                    int mk0 = mask[bb * SEQ + ng];
                    int mk1 = mask[bb * SEQ + ng + 1];
                    float2 w;
                    w.x = mk0 ? -1e9f : v0 * 0.125f;
                    w.y = mk1 ? -1e9f : v1 * 0.125f;
                    *(float2*)(outp + ((size_t)z * SEQ + m) * SEQ + ng) = w;
                } else {
                    float2 w = {v0, v1};
                    *(float2*)(outp + (size_t)m * DM + ng) = w;
                }
            }
        }
    }
}

// ---------------------------------------------------------------------------
// ctx = attn @ V  (NN).  Per head: M=2048, N=64, K=2048.
// Block 128x64, 8 warps (4x2), warp tile 32x32, BK=16, double-buffered.
// ---------------------------------------------------------------------------
__global__ void __launch_bounds__(256)
ctx_kernel(const float* __restrict__ attn)
{
    __shared__ uint32_t AsH[2][8][SP], AsL[2][8][SP];
    __shared__ uint32_t BsH[2][8][72], BsL[2][8][72];

    const int t  = threadIdx.x;
    const int z  = blockIdx.z;                 // bh
    const int m0 = blockIdx.y * 128;
    const float* A = attn + (size_t)z * SEQ * SEQ;
    const float* V = g_v  + (size_t)z * SEQ * DK;

    const int lrow = t >> 1;
    const int kc   = (t & 1) * 8;
    const int k2b  = kc >> 1;
    const float* pA = A + (size_t)(m0 + lrow) * SEQ + kc;

    float4 ra0 = *(const float4*)(pA);
    float4 ra1 = *(const float4*)(pA + 4);
    float vb[2][2];
    #pragma unroll
    for (int i = 0; i < 2; i++) {
        int p = t + 256 * i;
        int pk2 = p >> 6, pn = p & 63;
        vb[i][0] = V[(size_t)(2 * pk2 + 0) * DK + pn];
        vb[i][1] = V[(size_t)(2 * pk2 + 1) * DK + pn];
    }

    split_pack(ra0.x, ra0.y, AsH[0][k2b + 0][lrow], AsL[0][k2b + 0][lrow]);
    split_pack(ra0.z, ra0.w, AsH[0][k2b + 1][lrow], AsL[0][k2b + 1][lrow]);
    split_pack(ra1.x, ra1.y, AsH[0][k2b + 2][lrow], AsL[0][k2b + 2][lrow]);
    split_pack(ra1.z, ra1.w, AsH[0][k2b + 3][lrow], AsL[0][k2b + 3][lrow]);
    #pragma unroll
    for (int i = 0; i < 2; i++) {
        int p = t + 256 * i;
        int pk2 = p >> 6, pn = p & 63;
        split_pack(vb[i][0], vb[i][1], BsH[0][pk2][pn], BsL[0][pk2][pn]);
    }
    __syncthreads();

    const int warp = t >> 5, lane = t & 31;
    const int wm = (warp >> 1) * 32;
    const int wn = (warp & 1) * 32;
    const int qrow = lane >> 2, qk = lane & 3;

    float c[2][4][4] = {};

    constexpr int NITER = SEQ / 16;            // 128
    for (int it = 0; it < NITER; ++it) {
        const int buf = it & 1;
        if (it + 1 < NITER) {
            const int k0 = (it + 1) * 16;
            const float* qa = pA + k0;
            ra0 = *(const float4*)(qa); ra1 = *(const float4*)(qa + 4);
            #pragma unroll
            for (int i = 0; i < 2; i++) {
                int p = t + 256 * i;
                int pk2 = p >> 6, pn = p & 63;
                vb[i][0] = V[(size_t)(k0 + 2 * pk2 + 0) * DK + pn];
                vb[i][1] = V[(size_t)(k0 + 2 * pk2 + 1) * DK + pn];
            }
        }

        uint32_t aH[2][4], aL[2][4], bH[4][2], bL[4][2];
        #pragma unroll
        for (int mt = 0; mt < 2; mt++) {
            int m = wm + mt * 16 + qrow;
            aH[mt][0] = AsH[buf][qk][m];     aH[mt][1] = AsH[buf][qk][m + 8];
            aH[mt][2] = AsH[buf][qk + 4][m]; aH[mt][3] = AsH[buf][qk + 4][m + 8];
            aL[mt][0] = AsL[buf][qk][m];     aL[mt][1] = AsL[buf][qk][m + 8];
            aL[mt][2] = AsL[buf][qk + 4][m]; aL[mt][3] = AsL[buf][qk + 4][m + 8];
        }
        #pragma unroll
        for (int nt = 0; nt < 4; nt++) {
            int n = wn + nt * 8 + qrow;
            bH[nt][0] = BsH[buf][qk][n]; bH[nt][1] = BsH[buf][qk + 4][n];
            bL[nt][0] = BsL[buf][qk][n]; bL[nt][1] = BsL[buf][qk + 4][n];
        }
        #pragma unroll
        for (int mt = 0; mt < 2; mt++)
            #pragma unroll
            for (int nt = 0; nt < 4; nt++) {
                mma_bf16(c[mt][nt], aH[mt], bH[nt]);
                mma_bf16(c[mt][nt], aH[mt], bL[nt]);
                mma_bf16(c[mt][nt], aL[mt], bH[nt]);
            }

        if (it + 1 < NITER) {
            const int nb = buf ^ 1;
            split_pack(ra0.x, ra0.y, AsH[nb][k2b + 0][lrow], AsL[nb][k2b + 0][lrow]);
            split_pack(ra0.z, ra0.w, AsH[nb][k2b + 1][lrow], AsL[nb][k2b + 1][lrow]);
            split_pack(ra1.x, ra1.y, AsH[nb][k2b + 2][lrow], AsL[nb][k2b + 2][lrow]);
            split_pack(ra1.z, ra1.w, AsH[nb][k2b + 3][lrow], AsL[nb][k2b + 3][lrow]);
            #pragma unroll
            for (int i = 0; i < 2; i++) {
                int p = t + 256 * i;
                int pk2 = p >> 6, pn = p & 63;
                split_pack(vb[i][0], vb[i][1], BsH[nb][pk2][pn], BsL[nb][pk2][pn]);
            }
        }
        __syncthreads();
    }

    const int b = z >> 4, h = z & 15;
    #pragma unroll
    for (int mt = 0; mt < 2; mt++) {
        #pragma unroll
        for (int nt = 0; nt < 4; nt++) {
            int s0 = m0 + wm + mt * 16 + qrow;
            int d  = wn + nt * 8 + qk * 2;
            #pragma unroll
            for (int half = 0; half < 2; half++) {
                int s = s0 + half * 8;
                float2 w = {c[mt][nt][half * 2 + 0], c[mt][nt][half * 2 + 1]};
                *(float2*)(g_ctx + ((size_t)b * SEQ + s) * DM + h * DK + d) = w;
            }
        }
    }
}

// ---------------------------------------------------------------------------
// Row softmax in place. One block (256 thr) per row of 2048.
// ---------------------------------------------------------------------------
__global__ void __launch_bounds__(256)
softmax_kernel(float* __restrict__ attn)
{
    float* p = attn + (size_t)blockIdx.x * SEQ;
    const int t = threadIdx.x;

    float vals[8];
    float mx = -INFINITY;
    #pragma unroll
    for (int c = 0; c < 2; c++) {
        float4 f = *(float4*)(p + c * 1024 + t * 4);
        vals[c * 4 + 0] = f.x; vals[c * 4 + 1] = f.y;
        vals[c * 4 + 2] = f.z; vals[c * 4 + 3] = f.w;
    }
    #pragma unroll
    for (int i = 0; i < 8; i++) mx = fmaxf(mx, vals[i]);

    __shared__ float sm[8];
    #pragma unroll
    for (int o = 16; o; o >>= 1) mx = fmaxf(mx, __shfl_xor_sync(0xffffffffu, mx, o));
    if ((t & 31) == 0) sm[t >> 5] = mx;
    __syncthreads();
    if (t < 32) {
        float v = (t < 8) ? sm[t] : -INFINITY;
        #pragma unroll
        for (int o = 4; o; o >>= 1) v = fmaxf(v, __shfl_xor_sync(0xffffffffu, v, o));
        if (t == 0) sm[0] = v;
    }
    __syncthreads();
    mx = sm[0];

    float s = 0.f;
    #pragma unroll
    for (int i = 0; i < 8; i++) { vals[i] = __expf(vals[i] - mx); s += vals[i]; }

    __shared__ float sm2[8];
    #pragma unroll
    for (int o = 16; o; o >>= 1) s += __shfl_xor_sync(0xffffffffu, s, o);
    if ((t & 31) == 0) sm2[t >> 5] = s;
    __syncthreads();
    if (t < 32) {
        float v = (t < 8) ? sm2[t] : 0.f;
        #pragma unroll
        for (int o = 4; o; o >>= 1) v += __shfl_xor_sync(0xffffffffu, v, o);
        if (t == 0) sm2[0] = v;
    }
    __syncthreads();
    const float inv = 1.0f / sm2[0];

    #pragma unroll
    for (int c = 0; c < 2; c++) {
        float4 f;
        f.x = vals[c * 4 + 0] * inv; f.y = vals[c * 4 + 1] * inv;
        f.z = vals[c * 4 + 2] * inv; f.w = vals[c * 4 + 3] * inv;
        *(float4*)(p + c * 1024 + t * 4) = f;
    }
}

// ---------------------------------------------------------------------------
// Launch. d_out layout: [out: 4096*1024 f32][attn: 32*2048*2048 f32]
// Inputs: x, mask, w_q, w_k, w_v, w_o
// ---------------------------------------------------------------------------
extern "C" void kernel_launch(void* const* d_in, const int* in_sizes, int n_in,
                              void* d_out, int out_size)
{
    const float* x    = (const float*)d_in[0];
    const int*   mask = (const int*)  d_in[1];
    const float* wq   = (const float*)d_in[2];
    const float* wk   = (const float*)d_in[3];
    const float* wv   = (const float*)d_in[4];
    const float* wo   = (const float*)d_in[5];

    float* out  = (float*)d_out;
    float* attn = out + (size_t)MROWS * DM;

    gemm_nt_kernel<0><<<dim3(DM / 128, MROWS / 128, 3), 256>>>(x, wq, wk, wv, nullptr, nullptr);
    gemm_nt_kernel<1><<<dim3(SEQ / 128, SEQ / 128, BH), 256>>>(nullptr, nullptr, nullptr, nullptr, mask, attn);
    softmax_kernel<<<BH * SEQ, 256>>>(attn);
    ctx_kernel<<<dim3(1, SEQ / 128, BH), 256>>>(attn);
    gemm_nt_kernel<2><<<dim3(DM / 128, MROWS / 128, 1), 256>>>(nullptr, wo, nullptr, nullptr, nullptr, out);
}